// round 1
// baseline (speedup 1.0000x reference)
#include <cuda_runtime.h>
#include <math.h>

// Problem constants
#define NN 50000          // nodes
#define NE 500000         // original edges
#define ET (NE + NN)      // edges + self loops = 550000
#define H1N 4
#define D1 256            // H1*C1
#define C2 64
#define IND 128

// ---------------- device scratch (static, no allocation) ----------------
__device__ float    g_h1[NN * D1];        // layer1 projected features
__device__ float    g_out1[NN * D1];      // layer1 aggregated output (then elu'd in place)
__device__ float    g_h2[NN * C2];        // layer2 projected features
__device__ float    g_ssrc1[NN * H1N];
__device__ float    g_sdst1[NN * H1N];
__device__ unsigned g_m1[NN * H1N];
__device__ float    g_den1[NN * H1N];
__device__ float    g_alpha1[ET * H1N];
__device__ float    g_ssrc2[NN];
__device__ float    g_sdst2[NN];
__device__ unsigned g_m2[NN];
__device__ float    g_den2[NN];
__device__ float    g_alpha2[ET];
__device__ float    g_cnt[NN];
__device__ float    g_sum[NN];
__device__ float    g_loop[NN];
__device__ float    g_eproj[8];           // [0..3]=layer1 heads, [4]=layer2

// ordered-float <-> uint monotonic map for atomicMax on floats
__device__ __forceinline__ unsigned f2u(float f) {
    unsigned u = __float_as_uint(f);
    return (u & 0x80000000u) ? ~u : (u | 0x80000000u);
}
__device__ __forceinline__ float u2f(unsigned u) {
    return (u & 0x80000000u) ? __uint_as_float(u & 0x7FFFFFFFu) : __uint_as_float(~u);
}

// ---------------- kernels ----------------

__global__ void k_reset(float* __restrict__ dout, const float* __restrict__ b2) {
    int i = blockIdx.x * blockDim.x + threadIdx.x;
    if (i < NN * D1) g_out1[i] = 0.f;
    if (i < NN * C2) dout[i] = b2[i & 63];     // init output with bias2
    if (i < NN * H1N) { g_den1[i] = 0.f; g_m1[i] = 0u; }
    if (i < NN) { g_den2[i] = 0.f; g_m2[i] = 0u; g_cnt[i] = 0.f; g_sum[i] = 0.f; }
}

__global__ void k_loopstat(const int* __restrict__ dst, const float* __restrict__ ea) {
    int i = blockIdx.x * blockDim.x + threadIdx.x;
    if (i >= NE) return;
    int d = dst[i];
    atomicAdd(&g_cnt[d], 1.f);
    atomicAdd(&g_sum[d], ea[i]);
}

__global__ void k_loopattr() {
    int i = blockIdx.x * blockDim.x + threadIdx.x;
    if (i < NN) g_loop[i] = g_sum[i] / fmaxf(g_cnt[i], 1.f);
}

__global__ void k_eproj(const float* __restrict__ We1, const float* __restrict__ ae1,
                        const float* __restrict__ We2, const float* __restrict__ ae2) {
    __shared__ float sm[256];
    int t = threadIdx.x;
    sm[t] = We1[t] * ae1[t];
    __syncthreads();
    if (t < 4) {
        float s = 0.f;
        for (int j = 0; j < 64; j++) s += sm[t * 64 + j];
        g_eproj[t] = s;
    }
    __syncthreads();
    if (t < 64) sm[t] = We2[t] * ae2[t];
    __syncthreads();
    if (t == 0) {
        float s = 0.f;
        for (int j = 0; j < 64; j++) s += sm[j];
        g_eproj[4] = s;
    }
}

// GEMM1: h1 = x @ W1  (per block: 4 nodes x 256 cols; thread = 4 cols of one node)
__global__ void k_gemm1(const float* __restrict__ x, const float* __restrict__ W1,
                        const float* __restrict__ as1, const float* __restrict__ ad1) {
    __shared__ float xs[4 * IND];
    int tid = threadIdx.x;
    int g = tid >> 6;          // node within block (0..3)
    int lane = tid & 63;       // float4 column (0..63)
    int nodeBase = blockIdx.x * 4;
    for (int i = tid; i < 4 * IND; i += 256) xs[i] = x[nodeBase * IND + i];
    __syncthreads();

    const float4* __restrict__ W4 = (const float4*)W1;
    const float* xr = xs + g * IND;
    float4 acc = make_float4(0.f, 0.f, 0.f, 0.f);
#pragma unroll 8
    for (int k = 0; k < IND; k++) {
        float xv = xr[k];
        float4 w = W4[k * 64 + lane];
        acc.x += xv * w.x; acc.y += xv * w.y; acc.z += xv * w.z; acc.w += xv * w.w;
    }
    int node = nodeBase + g;
    ((float4*)g_h1)[node * 64 + lane] = acc;

    float4 av = ((const float4*)as1)[lane];
    float4 dv = ((const float4*)ad1)[lane];
    float ps = acc.x * av.x + acc.y * av.y + acc.z * av.z + acc.w * av.w;
    float pd = acc.x * dv.x + acc.y * dv.y + acc.z * dv.z + acc.w * dv.w;
#pragma unroll
    for (int off = 8; off; off >>= 1) {
        ps += __shfl_xor_sync(0xffffffffu, ps, off);
        pd += __shfl_xor_sync(0xffffffffu, pd, off);
    }
    if ((lane & 15) == 0) {
        int h = lane >> 4;
        g_ssrc1[node * 4 + h] = ps;
        g_sdst1[node * 4 + h] = pd;
    }
}

__global__ void k_alpha1(const int* __restrict__ src, const int* __restrict__ dst,
                         const float* __restrict__ ea) {
    int e = blockIdx.x * blockDim.x + threadIdx.x;
    if (e >= ET) return;
    int s, d; float a;
    if (e < NE) { s = src[e]; d = dst[e]; a = ea[e]; }
    else { s = e - NE; d = s; a = g_loop[s]; }
    float4 ss = ((const float4*)g_ssrc1)[s];
    float4 sd = ((const float4*)g_sdst1)[d];
    float4 al;
    al.x = ss.x + sd.x + a * g_eproj[0];
    al.y = ss.y + sd.y + a * g_eproj[1];
    al.z = ss.z + sd.z + a * g_eproj[2];
    al.w = ss.w + sd.w + a * g_eproj[3];
    al.x = al.x > 0.f ? al.x : 0.2f * al.x;
    al.y = al.y > 0.f ? al.y : 0.2f * al.y;
    al.z = al.z > 0.f ? al.z : 0.2f * al.z;
    al.w = al.w > 0.f ? al.w : 0.2f * al.w;
    ((float4*)g_alpha1)[e] = al;
    int b = d * 4;
    atomicMax(&g_m1[b + 0], f2u(al.x));
    atomicMax(&g_m1[b + 1], f2u(al.y));
    atomicMax(&g_m1[b + 2], f2u(al.z));
    atomicMax(&g_m1[b + 3], f2u(al.w));
}

__global__ void k_exp1(const int* __restrict__ dst) {
    int e = blockIdx.x * blockDim.x + threadIdx.x;
    if (e >= ET) return;
    int d = (e < NE) ? dst[e] : (e - NE);
    float4 al = ((const float4*)g_alpha1)[e];
    uint4 mu = ((const uint4*)g_m1)[d];
    al.x = __expf(al.x - u2f(mu.x));
    al.y = __expf(al.y - u2f(mu.y));
    al.z = __expf(al.z - u2f(mu.z));
    al.w = __expf(al.w - u2f(mu.w));
    int b = d * 4;
    atomicAdd(&g_den1[b + 0], al.x);
    atomicAdd(&g_den1[b + 1], al.y);
    atomicAdd(&g_den1[b + 2], al.z);
    atomicAdd(&g_den1[b + 3], al.w);
    ((float4*)g_alpha1)[e] = al;
}

// scatter1: out1[dst] += h1[src] * alpha/denom  -- 64 threads per edge (float4 each)
__global__ void k_scatter1(const int* __restrict__ src, const int* __restrict__ dst) {
    int tid = threadIdx.x;
    int e = blockIdx.x * 4 + (tid >> 6);
    int lane = tid & 63;
    int s, d;
    if (e < NE) { s = src[e]; d = dst[e]; }
    else { s = e - NE; d = s; }
    int h = lane >> 4;
    float w = g_alpha1[e * 4 + h] / (g_den1[d * 4 + h] + 1e-16f);
    float4 v = ((const float4*)g_h1)[s * 64 + lane];
    float* o = g_out1 + d * D1 + lane * 4;
    atomicAdd(o + 0, v.x * w);
    atomicAdd(o + 1, v.y * w);
    atomicAdd(o + 2, v.z * w);
    atomicAdd(o + 3, v.w * w);
}

__global__ void k_elubias(const float* __restrict__ b1) {
    int i = blockIdx.x * blockDim.x + threadIdx.x;
    if (i >= NN * D1) return;
    float v = g_out1[i] + b1[i & 255];
    g_out1[i] = v > 0.f ? v : (__expf(v) - 1.f);
}

// GEMM2: h2 = elu_out @ W2  (per block: 16 nodes x 64 cols; thread = 4 cols of one node)
__global__ void k_gemm2(const float* __restrict__ W2,
                        const float* __restrict__ as2, const float* __restrict__ ad2) {
    __shared__ float xs[16 * D1];
    int tid = threadIdx.x;
    int g = tid >> 4;          // node within block (0..15)
    int q = tid & 15;          // float4 column (0..15)
    int nodeBase = blockIdx.x * 16;
    const float4* src4 = (const float4*)(g_out1 + nodeBase * D1);
    float4* xs4 = (float4*)xs;
    for (int i = tid; i < 16 * D1 / 4; i += 256) xs4[i] = src4[i];
    __syncthreads();

    const float4* __restrict__ W4 = (const float4*)W2;
    const float* xr = xs + g * D1;
    float4 acc = make_float4(0.f, 0.f, 0.f, 0.f);
#pragma unroll 8
    for (int k = 0; k < D1; k++) {
        float xv = xr[k];
        float4 w = W4[k * 16 + q];
        acc.x += xv * w.x; acc.y += xv * w.y; acc.z += xv * w.z; acc.w += xv * w.w;
    }
    int node = nodeBase + g;
    ((float4*)g_h2)[node * 16 + q] = acc;

    float4 av = ((const float4*)as2)[q];
    float4 dv = ((const float4*)ad2)[q];
    float ps = acc.x * av.x + acc.y * av.y + acc.z * av.z + acc.w * av.w;
    float pd = acc.x * dv.x + acc.y * dv.y + acc.z * dv.z + acc.w * dv.w;
#pragma unroll
    for (int off = 8; off; off >>= 1) {
        ps += __shfl_xor_sync(0xffffffffu, ps, off);
        pd += __shfl_xor_sync(0xffffffffu, pd, off);
    }
    if (q == 0) { g_ssrc2[node] = ps; g_sdst2[node] = pd; }
}

__global__ void k_alpha2(const int* __restrict__ src, const int* __restrict__ dst,
                         const float* __restrict__ ea) {
    int e = blockIdx.x * blockDim.x + threadIdx.x;
    if (e >= ET) return;
    int s, d; float a;
    if (e < NE) { s = src[e]; d = dst[e]; a = ea[e]; }
    else { s = e - NE; d = s; a = g_loop[s]; }
    float al = g_ssrc2[s] + g_sdst2[d] + a * g_eproj[4];
    al = al > 0.f ? al : 0.2f * al;
    g_alpha2[e] = al;
    atomicMax(&g_m2[d], f2u(al));
}

__global__ void k_exp2(const int* __restrict__ dst) {
    int e = blockIdx.x * blockDim.x + threadIdx.x;
    if (e >= ET) return;
    int d = (e < NE) ? dst[e] : (e - NE);
    float v = __expf(g_alpha2[e] - u2f(g_m2[d]));
    atomicAdd(&g_den2[d], v);
    g_alpha2[e] = v;
}

// scatter2: out[dst] += h2[src] * alpha/denom  -- 16 threads per edge (float4 each)
__global__ void k_scatter2(const int* __restrict__ src, const int* __restrict__ dst,
                           float* __restrict__ dout) {
    int tid = threadIdx.x;
    int e = blockIdx.x * 16 + (tid >> 4);
    int q = tid & 15;
    int s, d;
    if (e < NE) { s = src[e]; d = dst[e]; }
    else { s = e - NE; d = s; }
    float w = g_alpha2[e] / (g_den2[d] + 1e-16f);
    float4 v = ((const float4*)g_h2)[s * 16 + q];
    float* o = dout + d * C2 + q * 4;
    atomicAdd(o + 0, v.x * w);
    atomicAdd(o + 1, v.y * w);
    atomicAdd(o + 2, v.z * w);
    atomicAdd(o + 3, v.w * w);
}

// ---------------- launch ----------------
extern "C" void kernel_launch(void* const* d_in, const int* in_sizes, int n_in,
                              void* d_out, int out_size) {
    const float* x   = (const float*)d_in[0];
    const int*   ei  = (const int*)d_in[1];
    const float* ea  = (const float*)d_in[2];
    const float* W1  = (const float*)d_in[3];
    const float* We1 = (const float*)d_in[4];
    const float* as1 = (const float*)d_in[5];
    const float* ad1 = (const float*)d_in[6];
    const float* ae1 = (const float*)d_in[7];
    const float* b1  = (const float*)d_in[8];
    const float* W2  = (const float*)d_in[9];
    const float* We2 = (const float*)d_in[10];
    const float* as2 = (const float*)d_in[11];
    const float* ad2 = (const float*)d_in[12];
    const float* ae2 = (const float*)d_in[13];
    const float* b2  = (const float*)d_in[14];
    float* dout = (float*)d_out;

    const int* src = ei;
    const int* dst = ei + NE;

    k_reset<<<(NN * D1) / 256, 256>>>(dout, b2);
    k_loopstat<<<(NE + 255) / 256, 256>>>(dst, ea);
    k_loopattr<<<(NN + 255) / 256, 256>>>();
    k_eproj<<<1, 256>>>(We1, ae1, We2, ae2);

    k_gemm1<<<NN / 4, 256>>>(x, W1, as1, ad1);
    k_alpha1<<<(ET + 255) / 256, 256>>>(src, dst, ea);
    k_exp1<<<(ET + 255) / 256, 256>>>(dst);
    k_scatter1<<<ET / 4, 256>>>(src, dst);
    k_elubias<<<(NN * D1) / 256, 256>>>(b1);

    k_gemm2<<<NN / 16, 256>>>(W2, as2, ad2);
    k_alpha2<<<(ET + 255) / 256, 256>>>(src, dst, ea);
    k_exp2<<<(ET + 255) / 256, 256>>>(dst);
    k_scatter2<<<ET / 16, 256>>>(src, dst, dout);
}

// round 2
// speedup vs baseline: 1.0018x; 1.0018x over previous
#include <cuda_runtime.h>
#include <math.h>

// Problem constants
#define NN 50000          // nodes
#define NE 500000         // original edges
#define ET (NE + NN)      // edges + self loops = 550000
#define H1N 4
#define D1 256            // H1*C1
#define C2 64
#define IND 128

// ---------------- device scratch (static, no allocation) ----------------
__device__ float    g_h1[NN * D1];        // layer1 projected features
__device__ float    g_out1[NN * D1];      // layer1 aggregated output (then elu'd in place)
__device__ float    g_h2[NN * C2];        // layer2 projected features
__device__ float    g_ssrc1[NN * H1N];
__device__ float    g_sdst1[NN * H1N];
__device__ unsigned g_m1[NN * H1N];
__device__ float    g_den1[NN * H1N];
__device__ float    g_alpha1[ET * H1N];
__device__ float    g_ssrc2[NN];
__device__ float    g_sdst2[NN];
__device__ unsigned g_m2[NN];
__device__ float    g_den2[NN];
__device__ float    g_alpha2[ET];
__device__ float    g_cnt[NN];
__device__ float    g_sum[NN];
__device__ float    g_loop[NN];
__device__ float    g_eproj[8];           // [0..3]=layer1 heads, [4]=layer2

// ordered-float <-> uint monotonic map for atomicMax on floats
__device__ __forceinline__ unsigned f2u(float f) {
    unsigned u = __float_as_uint(f);
    return (u & 0x80000000u) ? ~u : (u | 0x80000000u);
}
__device__ __forceinline__ float u2f(unsigned u) {
    return (u & 0x80000000u) ? __uint_as_float(u & 0x7FFFFFFFu) : __uint_as_float(~u);
}

// ---------------- kernels ----------------

__global__ void k_reset(float* __restrict__ dout, const float* __restrict__ b2) {
    int i = blockIdx.x * blockDim.x + threadIdx.x;
    if (i < NN * D1) g_out1[i] = 0.f;
    if (i < NN * C2) dout[i] = b2[i & 63];     // init output with bias2
    if (i < NN * H1N) { g_den1[i] = 0.f; g_m1[i] = 0u; }
    if (i < NN) { g_den2[i] = 0.f; g_m2[i] = 0u; g_cnt[i] = 0.f; g_sum[i] = 0.f; }
}

__global__ void k_loopstat(const int* __restrict__ dst, const float* __restrict__ ea) {
    int i = blockIdx.x * blockDim.x + threadIdx.x;
    if (i >= NE) return;
    int d = dst[i];
    atomicAdd(&g_cnt[d], 1.f);
    atomicAdd(&g_sum[d], ea[i]);
}

__global__ void k_loopattr() {
    int i = blockIdx.x * blockDim.x + threadIdx.x;
    if (i < NN) g_loop[i] = g_sum[i] / fmaxf(g_cnt[i], 1.f);
}

__global__ void k_eproj(const float* __restrict__ We1, const float* __restrict__ ae1,
                        const float* __restrict__ We2, const float* __restrict__ ae2) {
    __shared__ float sm[256];
    int t = threadIdx.x;
    sm[t] = We1[t] * ae1[t];
    __syncthreads();
    if (t < 4) {
        float s = 0.f;
        for (int j = 0; j < 64; j++) s += sm[t * 64 + j];
        g_eproj[t] = s;
    }
    __syncthreads();
    if (t < 64) sm[t] = We2[t] * ae2[t];
    __syncthreads();
    if (t == 0) {
        float s = 0.f;
        for (int j = 0; j < 64; j++) s += sm[j];
        g_eproj[4] = s;
    }
}

// GEMM1: h1 = x @ W1  (per block: 4 nodes x 256 cols; thread = 4 cols of one node)
__global__ void k_gemm1(const float* __restrict__ x, const float* __restrict__ W1,
                        const float* __restrict__ as1, const float* __restrict__ ad1) {
    __shared__ float xs[4 * IND];
    int tid = threadIdx.x;
    int g = tid >> 6;          // node within block (0..3)
    int lane = tid & 63;       // float4 column (0..63)
    int nodeBase = blockIdx.x * 4;
    for (int i = tid; i < 4 * IND; i += 256) xs[i] = x[nodeBase * IND + i];
    __syncthreads();

    const float4* __restrict__ W4 = (const float4*)W1;
    const float* xr = xs + g * IND;
    float4 acc = make_float4(0.f, 0.f, 0.f, 0.f);
#pragma unroll 8
    for (int k = 0; k < IND; k++) {
        float xv = xr[k];
        float4 w = W4[k * 64 + lane];
        acc.x += xv * w.x; acc.y += xv * w.y; acc.z += xv * w.z; acc.w += xv * w.w;
    }
    int node = nodeBase + g;
    ((float4*)g_h1)[node * 64 + lane] = acc;

    float4 av = ((const float4*)as1)[lane];
    float4 dv = ((const float4*)ad1)[lane];
    float ps = acc.x * av.x + acc.y * av.y + acc.z * av.z + acc.w * av.w;
    float pd = acc.x * dv.x + acc.y * dv.y + acc.z * dv.z + acc.w * dv.w;
#pragma unroll
    for (int off = 8; off; off >>= 1) {
        ps += __shfl_xor_sync(0xffffffffu, ps, off);
        pd += __shfl_xor_sync(0xffffffffu, pd, off);
    }
    if ((lane & 15) == 0) {
        int h = lane >> 4;
        g_ssrc1[node * 4 + h] = ps;
        g_sdst1[node * 4 + h] = pd;
    }
}

__global__ void k_alpha1(const int* __restrict__ src, const int* __restrict__ dst,
                         const float* __restrict__ ea) {
    int e = blockIdx.x * blockDim.x + threadIdx.x;
    if (e >= ET) return;
    int s, d; float a;
    if (e < NE) { s = src[e]; d = dst[e]; a = ea[e]; }
    else { s = e - NE; d = s; a = g_loop[s]; }
    float4 ss = ((const float4*)g_ssrc1)[s];
    float4 sd = ((const float4*)g_sdst1)[d];
    float4 al;
    al.x = ss.x + sd.x + a * g_eproj[0];
    al.y = ss.y + sd.y + a * g_eproj[1];
    al.z = ss.z + sd.z + a * g_eproj[2];
    al.w = ss.w + sd.w + a * g_eproj[3];
    al.x = al.x > 0.f ? al.x : 0.2f * al.x;
    al.y = al.y > 0.f ? al.y : 0.2f * al.y;
    al.z = al.z > 0.f ? al.z : 0.2f * al.z;
    al.w = al.w > 0.f ? al.w : 0.2f * al.w;
    ((float4*)g_alpha1)[e] = al;
    int b = d * 4;
    atomicMax(&g_m1[b + 0], f2u(al.x));
    atomicMax(&g_m1[b + 1], f2u(al.y));
    atomicMax(&g_m1[b + 2], f2u(al.z));
    atomicMax(&g_m1[b + 3], f2u(al.w));
}

__global__ void k_exp1(const int* __restrict__ dst) {
    int e = blockIdx.x * blockDim.x + threadIdx.x;
    if (e >= ET) return;
    int d = (e < NE) ? dst[e] : (e - NE);
    float4 al = ((const float4*)g_alpha1)[e];
    uint4 mu = ((const uint4*)g_m1)[d];
    al.x = __expf(al.x - u2f(mu.x));
    al.y = __expf(al.y - u2f(mu.y));
    al.z = __expf(al.z - u2f(mu.z));
    al.w = __expf(al.w - u2f(mu.w));
    int b = d * 4;
    atomicAdd(&g_den1[b + 0], al.x);
    atomicAdd(&g_den1[b + 1], al.y);
    atomicAdd(&g_den1[b + 2], al.z);
    atomicAdd(&g_den1[b + 3], al.w);
    ((float4*)g_alpha1)[e] = al;
}

// scatter1: out1[dst] += h1[src] * alpha/denom  -- 64 threads per edge (float4 each)
__global__ void k_scatter1(const int* __restrict__ src, const int* __restrict__ dst) {
    int tid = threadIdx.x;
    int e = blockIdx.x * 4 + (tid >> 6);
    int lane = tid & 63;
    int s, d;
    if (e < NE) { s = src[e]; d = dst[e]; }
    else { s = e - NE; d = s; }
    int h = lane >> 4;
    float w = g_alpha1[e * 4 + h] / (g_den1[d * 4 + h] + 1e-16f);
    float4 v = ((const float4*)g_h1)[s * 64 + lane];
    float* o = g_out1 + d * D1 + lane * 4;
    atomicAdd(o + 0, v.x * w);
    atomicAdd(o + 1, v.y * w);
    atomicAdd(o + 2, v.z * w);
    atomicAdd(o + 3, v.w * w);
}

__global__ void k_elubias(const float* __restrict__ b1) {
    int i = blockIdx.x * blockDim.x + threadIdx.x;
    if (i >= NN * D1) return;
    float v = g_out1[i] + b1[i & 255];
    g_out1[i] = v > 0.f ? v : (__expf(v) - 1.f);
}

// GEMM2: h2 = elu_out @ W2  (per block: 16 nodes x 64 cols; thread = 4 cols of one node)
__global__ void k_gemm2(const float* __restrict__ W2,
                        const float* __restrict__ as2, const float* __restrict__ ad2) {
    __shared__ float xs[16 * D1];
    int tid = threadIdx.x;
    int g = tid >> 4;          // node within block (0..15)
    int q = tid & 15;          // float4 column (0..15)
    int nodeBase = blockIdx.x * 16;
    const float4* src4 = (const float4*)(g_out1 + nodeBase * D1);
    float4* xs4 = (float4*)xs;
    for (int i = tid; i < 16 * D1 / 4; i += 256) xs4[i] = src4[i];
    __syncthreads();

    const float4* __restrict__ W4 = (const float4*)W2;
    const float* xr = xs + g * D1;
    float4 acc = make_float4(0.f, 0.f, 0.f, 0.f);
#pragma unroll 8
    for (int k = 0; k < D1; k++) {
        float xv = xr[k];
        float4 w = W4[k * 16 + q];
        acc.x += xv * w.x; acc.y += xv * w.y; acc.z += xv * w.z; acc.w += xv * w.w;
    }
    int node = nodeBase + g;
    ((float4*)g_h2)[node * 16 + q] = acc;

    float4 av = ((const float4*)as2)[q];
    float4 dv = ((const float4*)ad2)[q];
    float ps = acc.x * av.x + acc.y * av.y + acc.z * av.z + acc.w * av.w;
    float pd = acc.x * dv.x + acc.y * dv.y + acc.z * dv.z + acc.w * dv.w;
#pragma unroll
    for (int off = 8; off; off >>= 1) {
        ps += __shfl_xor_sync(0xffffffffu, ps, off);
        pd += __shfl_xor_sync(0xffffffffu, pd, off);
    }
    if (q == 0) { g_ssrc2[node] = ps; g_sdst2[node] = pd; }
}

__global__ void k_alpha2(const int* __restrict__ src, const int* __restrict__ dst,
                         const float* __restrict__ ea) {
    int e = blockIdx.x * blockDim.x + threadIdx.x;
    if (e >= ET) return;
    int s, d; float a;
    if (e < NE) { s = src[e]; d = dst[e]; a = ea[e]; }
    else { s = e - NE; d = s; a = g_loop[s]; }
    float al = g_ssrc2[s] + g_sdst2[d] + a * g_eproj[4];
    al = al > 0.f ? al : 0.2f * al;
    g_alpha2[e] = al;
    atomicMax(&g_m2[d], f2u(al));
}

__global__ void k_exp2(const int* __restrict__ dst) {
    int e = blockIdx.x * blockDim.x + threadIdx.x;
    if (e >= ET) return;
    int d = (e < NE) ? dst[e] : (e - NE);
    float v = __expf(g_alpha2[e] - u2f(g_m2[d]));
    atomicAdd(&g_den2[d], v);
    g_alpha2[e] = v;
}

// scatter2: out[dst] += h2[src] * alpha/denom  -- 16 threads per edge (float4 each)
__global__ void k_scatter2(const int* __restrict__ src, const int* __restrict__ dst,
                           float* __restrict__ dout) {
    int tid = threadIdx.x;
    int e = blockIdx.x * 16 + (tid >> 4);
    int q = tid & 15;
    int s, d;
    if (e < NE) { s = src[e]; d = dst[e]; }
    else { s = e - NE; d = s; }
    float w = g_alpha2[e] / (g_den2[d] + 1e-16f);
    float4 v = ((const float4*)g_h2)[s * 16 + q];
    float* o = dout + d * C2 + q * 4;
    atomicAdd(o + 0, v.x * w);
    atomicAdd(o + 1, v.y * w);
    atomicAdd(o + 2, v.z * w);
    atomicAdd(o + 3, v.w * w);
}

// ---------------- launch ----------------
extern "C" void kernel_launch(void* const* d_in, const int* in_sizes, int n_in,
                              void* d_out, int out_size) {
    const float* x   = (const float*)d_in[0];
    const int*   ei  = (const int*)d_in[1];
    const float* ea  = (const float*)d_in[2];
    const float* W1  = (const float*)d_in[3];
    const float* We1 = (const float*)d_in[4];
    const float* as1 = (const float*)d_in[5];
    const float* ad1 = (const float*)d_in[6];
    const float* ae1 = (const float*)d_in[7];
    const float* b1  = (const float*)d_in[8];
    const float* W2  = (const float*)d_in[9];
    const float* We2 = (const float*)d_in[10];
    const float* as2 = (const float*)d_in[11];
    const float* ad2 = (const float*)d_in[12];
    const float* ae2 = (const float*)d_in[13];
    const float* b2  = (const float*)d_in[14];
    float* dout = (float*)d_out;

    const int* src = ei;
    const int* dst = ei + NE;

    k_reset<<<(NN * D1) / 256, 256>>>(dout, b2);
    k_loopstat<<<(NE + 255) / 256, 256>>>(dst, ea);
    k_loopattr<<<(NN + 255) / 256, 256>>>();
    k_eproj<<<1, 256>>>(We1, ae1, We2, ae2);

    k_gemm1<<<NN / 4, 256>>>(x, W1, as1, ad1);
    k_alpha1<<<(ET + 255) / 256, 256>>>(src, dst, ea);
    k_exp1<<<(ET + 255) / 256, 256>>>(dst);
    k_scatter1<<<ET / 4, 256>>>(src, dst);
    k_elubias<<<(NN * D1) / 256, 256>>>(b1);

    k_gemm2<<<NN / 16, 256>>>(W2, as2, ad2);
    k_alpha2<<<(ET + 255) / 256, 256>>>(src, dst, ea);
    k_exp2<<<(ET + 255) / 256, 256>>>(dst);
    k_scatter2<<<ET / 16, 256>>>(src, dst, dout);
}